// round 10
// baseline (speedup 1.0000x reference)
#include <cuda_runtime.h>
#include <cuda_bf16.h>
#include <math_constants.h>
#include <cstdint>

// ---------------------------------------------------------------------------
// att = softmax( MLP3(concat(node1, u_rep)) ), N = 200000, d = 128.
// Single fused persistent kernel, 256 threads (8 warps, 4M x 2N warp grid):
//   - u_rep half of layer 1 folded into fp32 cvec (computed in-kernel)
//   - weights split bf16 hi/lo in-kernel, packed 16B frags [bh0 bh1 bl0 bl1]
//   - GEMMs via bf16x3 on mma.sync:  D = Ah*Bh + Al*Bh + Ah*Bl
//   - A-tile hazards guarded by PER-ROW-GROUP named barriers (64 threads),
//     so the 4 M-groups pipeline against each other; only the cross-warpN
//     logit reduction uses full __syncthreads (2 per tile instead of 5).
//   - logits in registers; grid-wide barrier; fused softmax + normalize
// ---------------------------------------------------------------------------

#define EMB     128
#define TILE    128
#define LMAX    16      // max tiles per CTA (ceil(1563/148) = 11)
#define GMAX    256
#define THREADS 256

// ---- smem layout (bytes) ----
#define OFF_W1   0        // 64KB: W1 frag-packed, 16B/frag = [bh0 bh1 bl0 bl1]
#define OFF_W2   65536    // 64KB
#define OFF_AH   131072   // 32KB
#define OFF_AL   163840   // 32KB
#define OFF_CVEC 196608
#define OFF_B2   197120
#define OFF_W3   197632
#define OFF_PART 198144   // 1KB (2 x 128 floats)
#define OFF_RED  199168   // 32B (8 floats)
#define SMEM_TOTAL 199232

// ---------------- device scratch ----------------
__device__ float        g_ctamax[GMAX];
__device__ float        g_ctasum[GMAX];
__device__ unsigned int g_bar;    // zero-init; reset in-kernel each run
__device__ unsigned int g_done;

__device__ __forceinline__ uint32_t b2u(__nv_bfloat162 h) {
    return *reinterpret_cast<uint32_t*>(&h);
}

// named barrier over one M-group (2 warps = 64 threads); ids 1..4
#define BARG(mid) asm volatile("bar.sync %0, 64;" :: "r"((mid) + 1) : "memory")

// mma.sync m16n8k16 bf16, fp32 accumulate in place (sm_80+ PTX)
__device__ __forceinline__ void mma_bf16(float* c, const uint32_t* a,
                                         uint32_t b0, uint32_t b1) {
    asm volatile("mma.sync.aligned.m16n8k16.row.col.f32.bf16.bf16.f32 "
        "{%0,%1,%2,%3}, {%4,%5,%6,%7}, {%8,%9}, {%0,%1,%2,%3};"
        : "+f"(c[0]), "+f"(c[1]), "+f"(c[2]), "+f"(c[3])
        : "r"(a[0]), "r"(a[1]), "r"(a[2]), "r"(a[3]), "r"(b0), "r"(b1));
}

// Weight fragment address (byte offset of the hi pair; lo pair at +8).
__device__ __forceinline__ int widx_hi(int n, int k) {
    int key = (((n >> 3) * 8 + (k >> 4)) * 32 + (n & 7) * 4 + ((k >> 1) & 3));
    int sub = ((k >> 3) & 1) * 2 + (k & 1);
    return key * 16 + sub * 2;
}

// ---------------------------------------------------------------------------
// One 128x128x128 layer slice: acc += Ah*Wh + Al*Wh + Ah*Wl  (bf16x3)
// Warp owns rows [warpM*32,+32), cols [warpN*64,+64).
// ---------------------------------------------------------------------------
__device__ __forceinline__ void run_layer(char* smc, int offW,
                                          float acc[2][8][4],
                                          int warpM, int warpN, int lane)
{
    #pragma unroll
    for (int ks = 0; ks < 8; ks++) {
        uint4 ah[2], al[2];
        #pragma unroll
        for (int mt = 0; mt < 2; mt++) {
            int mta  = warpM * 2 + mt;
            int aoff = ((mta * 8 + ks) * 32 + lane) * 16;
            ah[mt] = *(const uint4*)(smc + OFF_AH + aoff);
            al[mt] = *(const uint4*)(smc + OFF_AL + aoff);
        }
        #pragma unroll
        for (int j = 0; j < 8; j++) {
            int ntg  = warpN * 8 + j;
            int boff = ((ntg * 8 + ks) * 32 + lane) * 16;
            uint4 b = *(const uint4*)(smc + offW + boff);   // bh.x bh.y bl.x bl.y
            // interleave across mt for dep-distance-2 accumulate chains
            mma_bf16(acc[0][j], (const uint32_t*)&ah[0], b.x, b.y);
            mma_bf16(acc[1][j], (const uint32_t*)&ah[1], b.x, b.y);
            mma_bf16(acc[0][j], (const uint32_t*)&al[0], b.x, b.y);
            mma_bf16(acc[1][j], (const uint32_t*)&al[1], b.x, b.y);
            mma_bf16(acc[0][j], (const uint32_t*)&ah[0], b.z, b.w);
            mma_bf16(acc[1][j], (const uint32_t*)&ah[1], b.z, b.w);
        }
    }
}

// prefetch this warp's 16 rows of the node1 tile (rows warpM*32+warpN*16+it)
__device__ __forceinline__ void pfetch(const float4* __restrict__ n4, int base,
                                       int N, int rbase, int lane, float4 pf[16])
{
    #pragma unroll
    for (int it = 0; it < 16; it++) {
        float4 v = make_float4(0.f, 0.f, 0.f, 0.f);
        if (base >= 0) {
            int gr = base + rbase + it;
            if (gr < N) v = n4[(size_t)gr * 32 + lane];
        }
        pf[it] = v;
    }
}

// ---------------------------------------------------------------------------
__global__ __launch_bounds__(THREADS, 1)
void k_fused(const float* __restrict__ node1, const float* __restrict__ u_rep,
             const float* __restrict__ W1, const float* __restrict__ b1,
             const float* __restrict__ W2, const float* __restrict__ b2g,
             const float* __restrict__ w3g, const float* __restrict__ b3g,
             float* __restrict__ out, int N, int ntiles)
{
    extern __shared__ char smc[];
    const int tid   = threadIdx.x;
    const int wid   = tid >> 5;
    const int lane  = tid & 31;
    const int warpM = wid & 3;       // 4-way M split (32 rows each)
    const int warpN = wid >> 2;      // 2-way N split (64 cols each)
    const int g     = lane >> 2;
    const int t     = lane & 3;
    const int bid   = blockIdx.x;
    const unsigned G = gridDim.x;
    const int rbase = warpM * 32 + warpN * 16;   // this warp's staged rows

    float* s_cvec = (float*)(smc + OFF_CVEC);
    float* s_b2   = (float*)(smc + OFF_B2);
    float* s_w3   = (float*)(smc + OFF_W3);
    float* s_part = (float*)(smc + OFF_PART);
    float* s_red  = (float*)(smc + OFF_RED);

    // ---- in-kernel weight split (bf16 hi/lo), fragment-packed ----
    for (int i = tid; i < EMB * EMB; i += THREADS) {
        int n = i >> 7, k = i & 127;
        int off = widx_hi(n, k);
        float w1 = W1[n * 256 + k];                   // node1 half of W1
        __nv_bfloat16 h1 = __float2bfloat16(w1);
        *(__nv_bfloat16*)(smc + OFF_W1 + off)     = h1;
        *(__nv_bfloat16*)(smc + OFF_W1 + off + 8) =
            __float2bfloat16(w1 - __bfloat162float(h1));
        float w2 = W2[n * 128 + k];
        __nv_bfloat16 h2 = __float2bfloat16(w2);
        *(__nv_bfloat16*)(smc + OFF_W2 + off)     = h2;
        *(__nv_bfloat16*)(smc + OFF_W2 + off + 8) =
            __float2bfloat16(w2 - __bfloat162float(h2));
    }
    // cvec = u_rep @ W1b^T + b1 (fp32, exact path)
    if (tid < 128) {
        float acc = b1[tid];
        const float* w = W1 + tid * 256 + 128;
        #pragma unroll 8
        for (int kk = 0; kk < 128; kk++) acc += u_rep[kk] * w[kk];
        s_cvec[tid] = acc;
        s_b2[tid]   = b2g[tid];
        s_w3[tid]   = w3g[tid];
    }
    __syncthreads();

    const float fb3 = b3g[0];
    const float4* n4 = (const float4*)node1;

    const int nt = (ntiles > bid) ? (ntiles - 1 - bid) / (int)G + 1 : 0;
    float lg[LMAX];           // per-thread logits (tid<128)
    float runmax = -CUDART_INF_F;

    float4 pf[16];
    pfetch(n4, (0 < nt) ? (bid * TILE) : -1, N, rbase, lane, pf);

    for (int kt = 0; kt < nt; kt++) {
        const int tile = bid + kt * (int)G;
        const int base = tile * TILE;

        // ---- stage: split prefetched fp32 -> bf16 hi/lo, fragment-packed ----
        {
            const int ks  = lane >> 2;
            const int khi = (lane >> 1) & 1;
            const int t0  = (2 * lane) & 3;
            #pragma unroll
            for (int it = 0; it < 16; it++) {
                float4 v = pf[it];
                int r = rbase + it;
                __nv_bfloat162 h01 = __floats2bfloat162_rn(v.x, v.y);
                __nv_bfloat162 h23 = __floats2bfloat162_rn(v.z, v.w);
                __nv_bfloat162 l01 = __floats2bfloat162_rn(v.x - __bfloat162float(h01.x),
                                                           v.y - __bfloat162float(h01.y));
                __nv_bfloat162 l23 = __floats2bfloat162_rn(v.z - __bfloat162float(h23.x),
                                                           v.w - __bfloat162float(h23.y));
                int mta = r >> 4, gg = r & 7, half = (r >> 3) & 1;
                int cb = ((mta * 8 + ks) * 32 + gg * 4) * 16 + half * 4 + khi * 8;
                *(uint32_t*)(smc + OFF_AH + cb + t0 * 16)       = b2u(h01);
                *(uint32_t*)(smc + OFF_AL + cb + t0 * 16)       = b2u(l01);
                *(uint32_t*)(smc + OFF_AH + cb + (t0 + 1) * 16) = b2u(h23);
                *(uint32_t*)(smc + OFF_AL + cb + (t0 + 1) * 16) = b2u(l23);
            }
        }
        BARG(warpM);                 // group's A rows staged

        // prefetch next tile early: LDG latency hides under layer-1 MMAs
        {
            int tile2 = bid + (kt + 1) * (int)G;
            pfetch(n4, (tile2 < ntiles) ? tile2 * TILE : -1, N, rbase, lane, pf);
        }

        // ---- layer 1 ----
        float acc[2][8][4];
        #pragma unroll
        for (int mt = 0; mt < 2; mt++)
            #pragma unroll
            for (int j = 0; j < 8; j++)
                #pragma unroll
                for (int e = 0; e < 4; e++) acc[mt][j][e] = 0.f;

        run_layer(smc, OFF_W1, acc, warpM, warpN, lane);
        BARG(warpM);                 // group's A rows fully consumed

        // ---- epilogue 1: relu(C + cvec) -> bf16 hi/lo back into A rows ----
        #pragma unroll
        for (int mt = 0; mt < 2; mt++) {
            int mta = warpM * 2 + mt;
            #pragma unroll
            for (int j = 0; j < 8; j++) {
                int ntg  = warpN * 8 + j;
                int col0 = ntg * 8 + t * 2;
                float* c = acc[mt][j];
                float v0 = fmaxf(c[0] + s_cvec[col0],     0.f);
                float v1 = fmaxf(c[1] + s_cvec[col0 + 1], 0.f);
                float v2 = fmaxf(c[2] + s_cvec[col0],     0.f);
                float v3 = fmaxf(c[3] + s_cvec[col0 + 1], 0.f);
                __nv_bfloat162 h01 = __floats2bfloat162_rn(v0, v1);
                __nv_bfloat162 h23 = __floats2bfloat162_rn(v2, v3);
                __nv_bfloat162 l01 = __floats2bfloat162_rn(v0 - __bfloat162float(h01.x),
                                                           v1 - __bfloat162float(h01.y));
                __nv_bfloat162 l23 = __floats2bfloat162_rn(v2 - __bfloat162float(h23.x),
                                                           v3 - __bfloat162float(h23.y));
                int cb = ((mta * 8 + (ntg >> 1)) * 32 + g * 4 + t) * 16 + (ntg & 1) * 8;
                *(uint2*)(smc + OFF_AH + cb) = make_uint2(b2u(h01), b2u(h23));
                *(uint2*)(smc + OFF_AL + cb) = make_uint2(b2u(l01), b2u(l23));
                c[0] = c[1] = c[2] = c[3] = 0.f;
            }
        }
        BARG(warpM);                 // group's h1 rows complete (both col halves)

        // ---- layer 2 ----
        run_layer(smc, OFF_W2, acc, warpM, warpN, lane);

        // ---- epilogue 2: relu(C + b2) dot w3 -> per-row partials ----
        float sp[2][2] = {{0.f, 0.f}, {0.f, 0.f}};   // [mt][half]
        #pragma unroll
        for (int mt = 0; mt < 2; mt++) {
            #pragma unroll
            for (int j = 0; j < 8; j++) {
                int ntg  = warpN * 8 + j;
                int col0 = ntg * 8 + t * 2;
                float* c = acc[mt][j];
                float w0 = s_w3[col0], w1 = s_w3[col0 + 1];
                float bb0 = s_b2[col0], bb1 = s_b2[col0 + 1];
                sp[mt][0] += fmaxf(c[0] + bb0, 0.f) * w0
                           + fmaxf(c[1] + bb1, 0.f) * w1;
                sp[mt][1] += fmaxf(c[2] + bb0, 0.f) * w0
                           + fmaxf(c[3] + bb1, 0.f) * w1;
            }
        }
        #pragma unroll
        for (int off = 1; off < 4; off <<= 1) {
            #pragma unroll
            for (int mt = 0; mt < 2; mt++) {
                sp[mt][0] += __shfl_xor_sync(0xffffffffu, sp[mt][0], off);
                sp[mt][1] += __shfl_xor_sync(0xffffffffu, sp[mt][1], off);
            }
        }
        if (t == 0) {
            #pragma unroll
            for (int mt = 0; mt < 2; mt++) {
                int rb = warpM * 32 + mt * 16;
                s_part[warpN * 128 + rb + g]     = sp[mt][0];
                s_part[warpN * 128 + rb + 8 + g] = sp[mt][1];
            }
        }
        __syncthreads();             // s_part complete across warpN

        if (tid < 128) {
            int gr = base + tid;
            float v = s_part[tid] + s_part[128 + tid] + fb3;
            lg[kt] = v;
            if (gr < N) runmax = fmaxf(runmax, v);
        }
        __syncthreads();             // s_part consumed before next tile
    }

    // ---- phase-1 end: per-CTA max ----
    float m = runmax;
    #pragma unroll
    for (int s = 16; s > 0; s >>= 1) m = fmaxf(m, __shfl_xor_sync(0xffffffffu, m, s));
    if (lane == 0) s_red[wid] = m;
    __syncthreads();
    if (tid == 0) {
        float mx = s_red[0];
        #pragma unroll
        for (int i = 1; i < 8; i++) mx = fmaxf(mx, s_red[i]);
        g_ctamax[bid] = mx;
        __threadfence();
        atomicAdd(&g_bar, 1u);
        while (atomicAdd(&g_bar, 0u) < G) __nanosleep(64);
        __threadfence();
    }
    __syncthreads();

    // ---- phase 2: global max (deterministic serial), exp, per-CTA sum ----
    float gmax = g_ctamax[0];
    for (unsigned i = 1; i < G; i++) gmax = fmaxf(gmax, g_ctamax[i]);

    float psum = 0.f;
    if (tid < 128) {
        for (int kt = 0; kt < nt; kt++) {
            int gr = (bid + kt * (int)G) * TILE + tid;
            if (gr < N) {
                float e = __expf(lg[kt] - gmax);
                lg[kt] = e;
                psum += e;
            }
        }
    }
    #pragma unroll
    for (int s = 16; s > 0; s >>= 1) psum += __shfl_xor_sync(0xffffffffu, psum, s);
    if (lane == 0) s_red[wid] = psum;
    __syncthreads();
    if (tid == 0) {
        float sm = 0.f;
        #pragma unroll
        for (int i = 0; i < 8; i++) sm += s_red[i];
        g_ctasum[bid] = sm;
        __threadfence();
        atomicAdd(&g_bar, 1u);
        while (atomicAdd(&g_bar, 0u) < 2u * G) __nanosleep(64);
        __threadfence();
    }
    __syncthreads();

    // ---- phase 3: total sum (deterministic serial), normalize, write ----
    float tot = 0.f;
    for (unsigned i = 0; i < G; i++) tot += g_ctasum[i];
    const float inv = 1.f / tot;

    if (tid < 128) {
        for (int kt = 0; kt < nt; kt++) {
            int gr = (bid + kt * (int)G) * TILE + tid;
            if (gr < N) out[gr] = lg[kt] * inv;
        }
    }

    // ---- reset barrier state for next graph replay ----
    __syncthreads();
    if (tid == 0) {
        unsigned d = atomicAdd(&g_done, 1u);
        if (d == G - 1u) {
            atomicExch(&g_bar, 0u);
            atomicExch(&g_done, 0u);
            __threadfence();
        }
    }
}

// ---------------------------------------------------------------------------
extern "C" void kernel_launch(void* const* d_in, const int* in_sizes, int n_in,
                              void* d_out, int out_size)
{
    const float* node1 = (const float*)d_in[0];
    const float* u_rep = (const float*)d_in[1];

    // inputs: node1, u_rep, [num_neighs], W1, b1, W2, b2, W3, b3
    int wi = (n_in >= 9) ? 2 + (n_in - 8) : 2;
    if (in_sizes[wi] != 128 * 256) {
        for (int i = 2; i + 5 < n_in; i++)
            if (in_sizes[i] == 128 * 256) { wi = i; break; }
    }
    const float* W1 = (const float*)d_in[wi + 0];
    const float* b1 = (const float*)d_in[wi + 1];
    const float* W2 = (const float*)d_in[wi + 2];
    const float* b2 = (const float*)d_in[wi + 3];
    const float* W3 = (const float*)d_in[wi + 4];
    const float* b3 = (const float*)d_in[wi + 5];
    float* out = (float*)d_out;

    const int N      = in_sizes[0] / EMB;
    const int ntiles = (N + TILE - 1) / TILE;

    int nsm = 0;
    cudaDeviceGetAttribute(&nsm, cudaDevAttrMultiProcessorCount, 0);
    if (nsm <= 0) nsm = 148;
    int grid = ntiles < nsm ? ntiles : nsm;
    if (grid > GMAX) grid = GMAX;

    cudaFuncSetAttribute(k_fused, cudaFuncAttributeMaxDynamicSharedMemorySize,
                         SMEM_TOTAL);
    k_fused<<<grid, THREADS, SMEM_TOTAL>>>(node1, u_rep, W1, b1, W2, b2, W3, b3,
                                           out, N, ntiles);
}

// round 11
// speedup vs baseline: 1.0814x; 1.0814x over previous
#include <cuda_runtime.h>
#include <cuda_bf16.h>
#include <math_constants.h>
#include <cstdint>

// ---------------------------------------------------------------------------
// att = softmax( MLP3(concat(node1, u_rep)) ), N = 200000, d = 128.
// Single fused persistent kernel (R6 structure), 256 threads, 4Mx2N warps:
//   - GEMMs via bf16x3 on mma.sync:  D = Ah*Bh + Al*Bh + Ah*Bl
//   - THIS ROUND: term-major, j-inner MMA ordering (dep distance 8) with
//     B hi/lo packed per-fragment (one LDS.128 per fragment).
// ---------------------------------------------------------------------------

#define EMB     128
#define TILE    128
#define LMAX    16
#define GMAX    256
#define THREADS 256

// ---- smem layout (bytes) ----
#define OFF_W1   0        // 64KB: W1 frag-packed, 16B/frag = [bh0 bh1 bl0 bl1]
#define OFF_W2   65536    // 64KB
#define OFF_AH   131072   // 32KB
#define OFF_AL   163840   // 32KB
#define OFF_CVEC 196608
#define OFF_B2   197120
#define OFF_W3   197632
#define OFF_PART 198144   // 1KB (2 x 128 floats)
#define OFF_RED  199168   // 32B
#define SMEM_TOTAL 199232

// ---------------- device scratch ----------------
__device__ float        g_ctamax[GMAX];
__device__ float        g_ctasum[GMAX];
__device__ unsigned int g_bar;
__device__ unsigned int g_done;

__device__ __forceinline__ uint32_t b2u(__nv_bfloat162 h) {
    return *reinterpret_cast<uint32_t*>(&h);
}

// mma.sync m16n8k16 bf16, fp32 accumulate in place (sm_80+ PTX)
__device__ __forceinline__ void mma_bf16(float* c, const uint32_t* a,
                                         uint32_t b0, uint32_t b1) {
    asm volatile("mma.sync.aligned.m16n8k16.row.col.f32.bf16.bf16.f32 "
        "{%0,%1,%2,%3}, {%4,%5,%6,%7}, {%8,%9}, {%0,%1,%2,%3};"
        : "+f"(c[0]), "+f"(c[1]), "+f"(c[2]), "+f"(c[3])
        : "r"(a[0]), "r"(a[1]), "r"(a[2]), "r"(a[3]), "r"(b0), "r"(b1));
}

// Weight fragment address (byte offset of hi pair; lo pair at +8).
// B[n][k] "col" operand: lane=(n&7)*4+((k>>1)&3), sub=((k>>3)&1)*2+(k&1).
__device__ __forceinline__ int widx_hi(int n, int k) {
    int key = (((n >> 3) * 8 + (k >> 4)) * 32 + (n & 7) * 4 + ((k >> 1) & 3));
    int sub = ((k >> 3) & 1) * 2 + (k & 1);
    return key * 16 + sub * 2;
}

// ---------------------------------------------------------------------------
// One 128x128x128 layer slice: acc += Ah*Wh + Al*Wh + Ah*Wl  (bf16x3)
// Term-major, j-inner ordering: same-acc reuse distance = 8 MMAs.
// ---------------------------------------------------------------------------
__device__ __forceinline__ void run_layer(char* smc, int offW,
                                          float acc[2][8][4],
                                          int warpM, int warpN, int lane)
{
    #pragma unroll
    for (int ks = 0; ks < 8; ks++) {
        uint4 ah[2], al[2];
        #pragma unroll
        for (int mt = 0; mt < 2; mt++) {
            int mta  = warpM * 2 + mt;
            int aoff = ((mta * 8 + ks) * 32 + lane) * 16;
            ah[mt] = *(const uint4*)(smc + OFF_AH + aoff);
            al[mt] = *(const uint4*)(smc + OFF_AL + aoff);
        }
        #pragma unroll
        for (int jb = 0; jb < 2; jb++) {
            uint4 b[4];
            #pragma unroll
            for (int j4 = 0; j4 < 4; j4++) {
                int ntg  = warpN * 8 + jb * 4 + j4;
                int boff = ((ntg * 8 + ks) * 32 + lane) * 16;
                b[j4] = *(const uint4*)(smc + offW + boff);  // bh.x bh.y bl.x bl.y
            }
            // 24 MMAs, dep distance 8 between same-accumulator uses
            #pragma unroll
            for (int j4 = 0; j4 < 4; j4++)
                mma_bf16(acc[0][jb * 4 + j4], (const uint32_t*)&ah[0], b[j4].x, b[j4].y);
            #pragma unroll
            for (int j4 = 0; j4 < 4; j4++)
                mma_bf16(acc[1][jb * 4 + j4], (const uint32_t*)&ah[1], b[j4].x, b[j4].y);
            #pragma unroll
            for (int j4 = 0; j4 < 4; j4++)
                mma_bf16(acc[0][jb * 4 + j4], (const uint32_t*)&al[0], b[j4].x, b[j4].y);
            #pragma unroll
            for (int j4 = 0; j4 < 4; j4++)
                mma_bf16(acc[1][jb * 4 + j4], (const uint32_t*)&al[1], b[j4].x, b[j4].y);
            #pragma unroll
            for (int j4 = 0; j4 < 4; j4++)
                mma_bf16(acc[0][jb * 4 + j4], (const uint32_t*)&ah[0], b[j4].z, b[j4].w);
            #pragma unroll
            for (int j4 = 0; j4 < 4; j4++)
                mma_bf16(acc[1][jb * 4 + j4], (const uint32_t*)&ah[1], b[j4].z, b[j4].w);
        }
    }
}

// prefetch one 128-row node1 tile into registers (16 float4 per thread)
__device__ __forceinline__ void pfetch(const float4* __restrict__ n4, int base,
                                       int N, int wid, int lane, float4 pf[16])
{
    #pragma unroll
    for (int it = 0; it < 16; it++) {
        float4 v = make_float4(0.f, 0.f, 0.f, 0.f);
        if (base >= 0) {
            int gr = base + it * 8 + wid;
            if (gr < N) v = n4[(size_t)gr * 32 + lane];
        }
        pf[it] = v;
    }
}

// ---------------------------------------------------------------------------
__global__ __launch_bounds__(THREADS, 1)
void k_fused(const float* __restrict__ node1, const float* __restrict__ u_rep,
             const float* __restrict__ W1, const float* __restrict__ b1,
             const float* __restrict__ W2, const float* __restrict__ b2g,
             const float* __restrict__ w3g, const float* __restrict__ b3g,
             float* __restrict__ out, int N, int ntiles)
{
    extern __shared__ char smc[];
    const int tid   = threadIdx.x;
    const int wid   = tid >> 5;
    const int lane  = tid & 31;
    const int warpM = wid & 3;       // 4-way M split (32 rows each)
    const int warpN = wid >> 2;      // 2-way N split (64 cols each)
    const int g     = lane >> 2;
    const int t     = lane & 3;
    const int bid   = blockIdx.x;
    const unsigned G = gridDim.x;

    float* s_cvec = (float*)(smc + OFF_CVEC);
    float* s_b2   = (float*)(smc + OFF_B2);
    float* s_w3   = (float*)(smc + OFF_W3);
    float* s_part = (float*)(smc + OFF_PART);
    float* s_red  = (float*)(smc + OFF_RED);

    // ---- in-kernel weight split (bf16 hi/lo), fragment-packed ----
    for (int i = tid; i < EMB * EMB; i += THREADS) {
        int n = i >> 7, k = i & 127;
        int off = widx_hi(n, k);
        float w1 = W1[n * 256 + k];                   // node1 half of W1
        __nv_bfloat16 h1 = __float2bfloat16(w1);
        *(__nv_bfloat16*)(smc + OFF_W1 + off)     = h1;
        *(__nv_bfloat16*)(smc + OFF_W1 + off + 8) =
            __float2bfloat16(w1 - __bfloat162float(h1));
        float w2 = W2[n * 128 + k];
        __nv_bfloat16 h2 = __float2bfloat16(w2);
        *(__nv_bfloat16*)(smc + OFF_W2 + off)     = h2;
        *(__nv_bfloat16*)(smc + OFF_W2 + off + 8) =
            __float2bfloat16(w2 - __bfloat162float(h2));
    }
    // cvec = u_rep @ W1b^T + b1 (fp32, exact path)
    if (tid < 128) {
        float acc = b1[tid];
        const float* w = W1 + tid * 256 + 128;
        #pragma unroll 8
        for (int kk = 0; kk < 128; kk++) acc += u_rep[kk] * w[kk];
        s_cvec[tid] = acc;
        s_b2[tid]   = b2g[tid];
        s_w3[tid]   = w3g[tid];
    }
    __syncthreads();

    const float fb3 = b3g[0];
    const float4* n4 = (const float4*)node1;

    const int nt = (ntiles > bid) ? (ntiles - 1 - bid) / (int)G + 1 : 0;
    float lg[LMAX];           // per-thread logits (tid<128)
    float runmax = -CUDART_INF_F;

    float4 pf[16];
    pfetch(n4, (0 < nt) ? (bid * TILE) : -1, N, wid, lane, pf);

    for (int kt = 0; kt < nt; kt++) {
        const int tile = bid + kt * (int)G;
        const int base = tile * TILE;

        // ---- stage: split prefetched fp32 -> bf16 hi/lo, fragment-packed ----
        #pragma unroll
        for (int it = 0; it < 16; it++) {
            float4 v = pf[it];
            int r = it * 8 + wid;      // row in tile
            int q = lane;              // float4 col index (k = 4q)
            __nv_bfloat162 h01 = __floats2bfloat162_rn(v.x, v.y);
            __nv_bfloat162 h23 = __floats2bfloat162_rn(v.z, v.w);
            __nv_bfloat162 l01 = __floats2bfloat162_rn(v.x - __bfloat162float(h01.x),
                                                       v.y - __bfloat162float(h01.y));
            __nv_bfloat162 l23 = __floats2bfloat162_rn(v.z - __bfloat162float(h23.x),
                                                       v.w - __bfloat162float(h23.y));
            int mt = r >> 4, gg = r & 7, half = (r >> 3) & 1;
            int ks = q >> 2, khi = (q >> 1) & 1;
            int t0 = (2 * q) & 3, t1 = (2 * q + 1) & 3;
            int cb = ((mt * 8 + ks) * 32 + gg * 4) * 16 + half * 4 + khi * 8;
            *(uint32_t*)(smc + OFF_AH + cb + t0 * 16) = b2u(h01);
            *(uint32_t*)(smc + OFF_AL + cb + t0 * 16) = b2u(l01);
            *(uint32_t*)(smc + OFF_AH + cb + t1 * 16) = b2u(h23);
            *(uint32_t*)(smc + OFF_AL + cb + t1 * 16) = b2u(l23);
        }
        __syncthreads();

        // ---- layer 1 ----
        float acc[2][8][4];
        #pragma unroll
        for (int mt = 0; mt < 2; mt++)
            #pragma unroll
            for (int j = 0; j < 8; j++)
                #pragma unroll
                for (int e = 0; e < 4; e++) acc[mt][j][e] = 0.f;

        run_layer(smc, OFF_W1, acc, warpM, warpN, lane);
        __syncthreads();                 // A consumed; may be rewritten

        // prefetch next tile while epilogue1 + layer2 run
        {
            int tile2 = bid + (kt + 1) * (int)G;
            pfetch(n4, (tile2 < ntiles) ? tile2 * TILE : -1, N, wid, lane, pf);
        }

        // ---- epilogue 1: relu(C + cvec) -> bf16 hi/lo back into A tiles ----
        #pragma unroll
        for (int mt = 0; mt < 2; mt++) {
            int mta = warpM * 2 + mt;
            #pragma unroll
            for (int j = 0; j < 8; j++) {
                int ntg  = warpN * 8 + j;
                int col0 = ntg * 8 + t * 2;
                float* c = acc[mt][j];
                float v0 = fmaxf(c[0] + s_cvec[col0],     0.f);
                float v1 = fmaxf(c[1] + s_cvec[col0 + 1], 0.f);
                float v2 = fmaxf(c[2] + s_cvec[col0],     0.f);
                float v3 = fmaxf(c[3] + s_cvec[col0 + 1], 0.f);
                __nv_bfloat162 h01 = __floats2bfloat162_rn(v0, v1);
                __nv_bfloat162 h23 = __floats2bfloat162_rn(v2, v3);
                __nv_bfloat162 l01 = __floats2bfloat162_rn(v0 - __bfloat162float(h01.x),
                                                           v1 - __bfloat162float(h01.y));
                __nv_bfloat162 l23 = __floats2bfloat162_rn(v2 - __bfloat162float(h23.x),
                                                           v3 - __bfloat162float(h23.y));
                int cb = ((mta * 8 + (ntg >> 1)) * 32 + g * 4 + t) * 16 + (ntg & 1) * 8;
                *(uint2*)(smc + OFF_AH + cb) = make_uint2(b2u(h01), b2u(h23));
                *(uint2*)(smc + OFF_AL + cb) = make_uint2(b2u(l01), b2u(l23));
                c[0] = c[1] = c[2] = c[3] = 0.f;
            }
        }
        __syncthreads();

        // ---- layer 2 ----
        run_layer(smc, OFF_W2, acc, warpM, warpN, lane);

        // ---- epilogue 2: relu(C + b2) dot w3 -> per-row partials ----
        float sp[2][2] = {{0.f, 0.f}, {0.f, 0.f}};   // [mt][half]
        #pragma unroll
        for (int mt = 0; mt < 2; mt++) {
            #pragma unroll
            for (int j = 0; j < 8; j++) {
                int ntg  = warpN * 8 + j;
                int col0 = ntg * 8 + t * 2;
                float* c = acc[mt][j];
                float w0 = s_w3[col0], w1 = s_w3[col0 + 1];
                float bb0 = s_b2[col0], bb1 = s_b2[col0 + 1];
                sp[mt][0] += fmaxf(c[0] + bb0, 0.f) * w0
                           + fmaxf(c[1] + bb1, 0.f) * w1;
                sp[mt][1] += fmaxf(c[2] + bb0, 0.f) * w0
                           + fmaxf(c[3] + bb1, 0.f) * w1;
            }
        }
        #pragma unroll
        for (int off = 1; off < 4; off <<= 1) {
            #pragma unroll
            for (int mt = 0; mt < 2; mt++) {
                sp[mt][0] += __shfl_xor_sync(0xffffffffu, sp[mt][0], off);
                sp[mt][1] += __shfl_xor_sync(0xffffffffu, sp[mt][1], off);
            }
        }
        if (t == 0) {
            #pragma unroll
            for (int mt = 0; mt < 2; mt++) {
                int rbase = warpM * 32 + mt * 16;
                s_part[warpN * 128 + rbase + g]     = sp[mt][0];
                s_part[warpN * 128 + rbase + 8 + g] = sp[mt][1];
            }
        }
        __syncthreads();

        if (tid < 128) {
            int gr = base + tid;
            float v = s_part[tid] + s_part[128 + tid] + fb3;
            lg[kt] = v;
            if (gr < N) runmax = fmaxf(runmax, v);
        }
        __syncthreads();
    }

    // ---- phase-1 end: per-CTA max ----
    float m = runmax;
    #pragma unroll
    for (int s = 16; s > 0; s >>= 1) m = fmaxf(m, __shfl_xor_sync(0xffffffffu, m, s));
    if (lane == 0) s_red[wid] = m;
    __syncthreads();
    if (tid == 0) {
        float mx = s_red[0];
        #pragma unroll
        for (int i = 1; i < 8; i++) mx = fmaxf(mx, s_red[i]);
        g_ctamax[bid] = mx;
        __threadfence();
        atomicAdd(&g_bar, 1u);
        while (atomicAdd(&g_bar, 0u) < G) __nanosleep(64);
        __threadfence();
    }
    __syncthreads();

    // ---- phase 2: global max (deterministic serial), exp, per-CTA sum ----
    float gmax = g_ctamax[0];
    for (unsigned i = 1; i < G; i++) gmax = fmaxf(gmax, g_ctamax[i]);

    float psum = 0.f;
    if (tid < 128) {
        for (int kt = 0; kt < nt; kt++) {
            int gr = (bid + kt * (int)G) * TILE + tid;
            if (gr < N) {
                float e = __expf(lg[kt] - gmax);
                lg[kt] = e;
                psum += e;
            }
        }
    }
    #pragma unroll
    for (int s = 16; s > 0; s >>= 1) psum += __shfl_xor_sync(0xffffffffu, psum, s);
    if (lane == 0) s_red[wid] = psum;
    __syncthreads();
    if (tid == 0) {
        float sm = 0.f;
        #pragma unroll
        for (int i = 0; i < 8; i++) sm += s_red[i];
        g_ctasum[bid] = sm;
        __threadfence();
        atomicAdd(&g_bar, 1u);
        while (atomicAdd(&g_bar, 0u) < 2u * G) __nanosleep(64);
        __threadfence();
    }
    __syncthreads();

    // ---- phase 3: total sum (deterministic serial), normalize, write ----
    float tot = 0.f;
    for (unsigned i = 0; i < G; i++) tot += g_ctasum[i];
    const float inv = 1.f / tot;

    if (tid < 128) {
        for (int kt = 0; kt < nt; kt++) {
            int gr = (bid + kt * (int)G) * TILE + tid;
            if (gr < N) out[gr] = lg[kt] * inv;
        }
    }

    // ---- reset barrier state for next graph replay ----
    __syncthreads();
    if (tid == 0) {
        unsigned d = atomicAdd(&g_done, 1u);
        if (d == G - 1u) {
            atomicExch(&g_bar, 0u);
            atomicExch(&g_done, 0u);
            __threadfence();
        }
    }
}

// ---------------------------------------------------------------------------
extern "C" void kernel_launch(void* const* d_in, const int* in_sizes, int n_in,
                              void* d_out, int out_size)
{
    const float* node1 = (const float*)d_in[0];
    const float* u_rep = (const float*)d_in[1];

    // inputs: node1, u_rep, [num_neighs], W1, b1, W2, b2, W3, b3
    int wi = (n_in >= 9) ? 2 + (n_in - 8) : 2;
    if (in_sizes[wi] != 128 * 256) {
        for (int i = 2; i + 5 < n_in; i++)
            if (in_sizes[i] == 128 * 256) { wi = i; break; }
    }
    const float* W1 = (const float*)d_in[wi + 0];
    const float* b1 = (const float*)d_in[wi + 1];
    const float* W2 = (const float*)d_in[wi + 2];
    const float* b2 = (const float*)d_in[wi + 3];
    const float* W3 = (const float*)d_in[wi + 4];
    const float* b3 = (const float*)d_in[wi + 5];
    float* out = (float*)d_out;

    const int N      = in_sizes[0] / EMB;
    const int ntiles = (N + TILE - 1) / TILE;

    int nsm = 0;
    cudaDeviceGetAttribute(&nsm, cudaDevAttrMultiProcessorCount, 0);
    if (nsm <= 0) nsm = 148;
    int grid = ntiles < nsm ? ntiles : nsm;
    if (grid > GMAX) grid = GMAX;

    cudaFuncSetAttribute(k_fused, cudaFuncAttributeMaxDynamicSharedMemorySize,
                         SMEM_TOTAL);
    k_fused<<<grid, THREADS, SMEM_TOTAL>>>(node1, u_rep, W1, b1, W2, b2, W3, b3,
                                           out, N, ntiles);
}

// round 12
// speedup vs baseline: 1.0937x; 1.0114x over previous
#include <cuda_runtime.h>
#include <cuda_bf16.h>
#include <math_constants.h>
#include <cstdint>

// ---------------------------------------------------------------------------
// att = softmax( MLP3(concat(node1, u_rep)) ), N = 200000, d = 128.
// Single fused persistent kernel, 256 threads, 4Mx2N warps, bf16x3 mma.sync.
// R11: fragment-assembly staging + merged epilogue stores -> ALL smem stores
//      are conflict-free STS.128; register prefetch removed (no spills).
// ---------------------------------------------------------------------------

#define EMB     128
#define TILE    128
#define LMAX    16
#define GMAX    256
#define THREADS 256

// ---- smem layout (bytes) ----
#define OFF_W1   0        // 64KB: W1 frag-packed, 16B/frag = [bh0 bh1 bl0 bl1]
#define OFF_W2   65536    // 64KB
#define OFF_AH   131072   // 32KB
#define OFF_AL   163840   // 32KB
#define OFF_CVEC 196608
#define OFF_B2   197120
#define OFF_W3   197632
#define OFF_PART 198144   // 1KB
#define OFF_RED  199168   // 32B
#define SMEM_TOTAL 199232

// ---------------- device scratch ----------------
__device__ float        g_ctamax[GMAX];
__device__ float        g_ctasum[GMAX];
__device__ unsigned int g_bar;
__device__ unsigned int g_done;

__device__ __forceinline__ uint32_t b2u(__nv_bfloat162 h) {
    return *reinterpret_cast<uint32_t*>(&h);
}

// mma.sync m16n8k16 bf16, fp32 accumulate in place (sm_80+ PTX)
__device__ __forceinline__ void mma_bf16(float* c, const uint32_t* a,
                                         uint32_t b0, uint32_t b1) {
    asm volatile("mma.sync.aligned.m16n8k16.row.col.f32.bf16.bf16.f32 "
        "{%0,%1,%2,%3}, {%4,%5,%6,%7}, {%8,%9}, {%0,%1,%2,%3};"
        : "+f"(c[0]), "+f"(c[1]), "+f"(c[2]), "+f"(c[3])
        : "r"(a[0]), "r"(a[1]), "r"(a[2]), "r"(a[3]), "r"(b0), "r"(b1));
}

// Weight fragment address (byte offset of hi pair; lo pair at +8).
__device__ __forceinline__ int widx_hi(int n, int k) {
    int key = (((n >> 3) * 8 + (k >> 4)) * 32 + (n & 7) * 4 + ((k >> 1) & 3));
    int sub = ((k >> 3) & 1) * 2 + (k & 1);
    return key * 16 + sub * 2;
}

// split helper: v -> (hi bf16, lo bf16) pair-packed
__device__ __forceinline__ void split2(float x, float y,
                                       uint32_t& h, uint32_t& l) {
    __nv_bfloat162 hh = __floats2bfloat162_rn(x, y);
    __nv_bfloat162 ll = __floats2bfloat162_rn(x - __bfloat162float(hh.x),
                                              y - __bfloat162float(hh.y));
    h = b2u(hh); l = b2u(ll);
}

// ---------------------------------------------------------------------------
// One 128x128x128 layer slice: acc += Ah*Wh + Al*Wh + Ah*Wl  (bf16x3)
// Term-major, j-inner ordering (dep distance 8).
// ---------------------------------------------------------------------------
__device__ __forceinline__ void run_layer(char* smc, int offW,
                                          float acc[2][8][4],
                                          int warpM, int warpN, int lane)
{
    #pragma unroll
    for (int ks = 0; ks < 8; ks++) {
        uint4 ah[2], al[2];
        #pragma unroll
        for (int mt = 0; mt < 2; mt++) {
            int mta  = warpM * 2 + mt;
            int aoff = ((mta * 8 + ks) * 32 + lane) * 16;
            ah[mt] = *(const uint4*)(smc + OFF_AH + aoff);
            al[mt] = *(const uint4*)(smc + OFF_AL + aoff);
        }
        #pragma unroll
        for (int jb = 0; jb < 2; jb++) {
            uint4 b[4];
            #pragma unroll
            for (int j4 = 0; j4 < 4; j4++) {
                int ntg  = warpN * 8 + jb * 4 + j4;
                int boff = ((ntg * 8 + ks) * 32 + lane) * 16;
                b[j4] = *(const uint4*)(smc + offW + boff);
            }
            #pragma unroll
            for (int j4 = 0; j4 < 4; j4++)
                mma_bf16(acc[0][jb * 4 + j4], (const uint32_t*)&ah[0], b[j4].x, b[j4].y);
            #pragma unroll
            for (int j4 = 0; j4 < 4; j4++)
                mma_bf16(acc[1][jb * 4 + j4], (const uint32_t*)&ah[1], b[j4].x, b[j4].y);
            #pragma unroll
            for (int j4 = 0; j4 < 4; j4++)
                mma_bf16(acc[0][jb * 4 + j4], (const uint32_t*)&al[0], b[j4].x, b[j4].y);
            #pragma unroll
            for (int j4 = 0; j4 < 4; j4++)
                mma_bf16(acc[1][jb * 4 + j4], (const uint32_t*)&al[1], b[j4].x, b[j4].y);
            #pragma unroll
            for (int j4 = 0; j4 < 4; j4++)
                mma_bf16(acc[0][jb * 4 + j4], (const uint32_t*)&ah[0], b[j4].z, b[j4].w);
            #pragma unroll
            for (int j4 = 0; j4 < 4; j4++)
                mma_bf16(acc[1][jb * 4 + j4], (const uint32_t*)&ah[1], b[j4].z, b[j4].w);
        }
    }
}

// ---------------------------------------------------------------------------
__global__ __launch_bounds__(THREADS, 1)
void k_fused(const float* __restrict__ node1, const float* __restrict__ u_rep,
             const float* __restrict__ W1, const float* __restrict__ b1,
             const float* __restrict__ W2, const float* __restrict__ b2g,
             const float* __restrict__ w3g, const float* __restrict__ b3g,
             float* __restrict__ out, int N, int ntiles)
{
    extern __shared__ char smc[];
    const int tid   = threadIdx.x;
    const int wid   = tid >> 5;
    const int lane  = tid & 31;
    const int warpM = wid & 3;       // 4-way M split (32 rows each)
    const int warpN = wid >> 2;      // 2-way N split (64 cols each)
    const int g     = lane >> 2;
    const int t     = lane & 3;
    const int bid   = blockIdx.x;
    const unsigned G = gridDim.x;

    float* s_cvec = (float*)(smc + OFF_CVEC);
    float* s_b2   = (float*)(smc + OFF_B2);
    float* s_w3   = (float*)(smc + OFF_W3);
    float* s_part = (float*)(smc + OFF_PART);
    float* s_red  = (float*)(smc + OFF_RED);

    // ---- in-kernel weight split (bf16 hi/lo), fragment-packed ----
    for (int i = tid; i < EMB * EMB; i += THREADS) {
        int n = i >> 7, k = i & 127;
        int off = widx_hi(n, k);
        float w1 = W1[n * 256 + k];                   // node1 half of W1
        __nv_bfloat16 h1 = __float2bfloat16(w1);
        *(__nv_bfloat16*)(smc + OFF_W1 + off)     = h1;
        *(__nv_bfloat16*)(smc + OFF_W1 + off + 8) =
            __float2bfloat16(w1 - __bfloat162float(h1));
        float w2 = W2[n * 128 + k];
        __nv_bfloat16 h2 = __float2bfloat16(w2);
        *(__nv_bfloat16*)(smc + OFF_W2 + off)     = h2;
        *(__nv_bfloat16*)(smc + OFF_W2 + off + 8) =
            __float2bfloat16(w2 - __bfloat162float(h2));
    }
    // cvec = u_rep @ W1b^T + b1 (fp32, exact path)
    if (tid < 128) {
        float acc = b1[tid];
        const float* w = W1 + tid * 256 + 128;
        #pragma unroll 8
        for (int kk = 0; kk < 128; kk++) acc += u_rep[kk] * w[kk];
        s_cvec[tid] = acc;
        s_b2[tid]   = b2g[tid];
        s_w3[tid]   = w3g[tid];
    }
    __syncthreads();

    const float fb3 = b3g[0];
    const int nt = (ntiles > bid) ? (ntiles - 1 - bid) / (int)G + 1 : 0;
    float lg[LMAX];
    float runmax = -CUDART_INF_F;

    for (int kt = 0; kt < nt; kt++) {
        const int tile = bid + kt * (int)G;
        const int base = tile * TILE;

        // ---- stage: assemble full 16B A-fragments, conflict-free STS.128 ----
        // warp `wid` owns keys wid*8+ks (rows [wid*16, wid*16+16)); lane=(g,t).
        {
            const int r0 = base + wid * 16 + g;      // half=0 row
            const int r1 = r0 + 8;                   // half=1 row
            const float2* p0 = (const float2*)(node1 + (size_t)r0 * 128) + t;
            const float2* p1 = (const float2*)(node1 + (size_t)r1 * 128) + t;
            const bool ok0 = (r0 < N), ok1 = (r1 < N);
            const float2 z = make_float2(0.f, 0.f);
            #pragma unroll
            for (int ks = 0; ks < 8; ks++) {
                // float2 at k = ks*16 + khi*8 + 2t  (float2 idx = ks*8+khi*4+t)
                float2 d00 = ok0 ? p0[ks * 8]     : z;   // half0, khi0
                float2 d01 = ok0 ? p0[ks * 8 + 4] : z;   // half0, khi1
                float2 d10 = ok1 ? p1[ks * 8]     : z;   // half1, khi0
                float2 d11 = ok1 ? p1[ks * 8 + 4] : z;   // half1, khi1
                uint4 H, L;
                split2(d00.x, d00.y, H.x, L.x);          // slot0 = khi0,half0
                split2(d10.x, d10.y, H.y, L.y);          // slot1 = khi0,half1
                split2(d01.x, d01.y, H.z, L.z);          // slot2 = khi1,half0
                split2(d11.x, d11.y, H.w, L.w);          // slot3 = khi1,half1
                int addr = ((wid * 8 + ks) * 32 + lane) * 16;
                *(uint4*)(smc + OFF_AH + addr) = H;
                *(uint4*)(smc + OFF_AL + addr) = L;
            }
        }
        __syncthreads();

        // ---- layer 1 ----
        float acc[2][8][4];
        #pragma unroll
        for (int mt = 0; mt < 2; mt++)
            #pragma unroll
            for (int j = 0; j < 8; j++)
                #pragma unroll
                for (int e = 0; e < 4; e++) acc[mt][j][e] = 0.f;

        run_layer(smc, OFF_W1, acc, warpM, warpN, lane);
        __syncthreads();                 // A consumed; may be rewritten

        // ---- epilogue 1: relu(C + cvec) -> full fragments, STS.128 ----
        #pragma unroll
        for (int mt = 0; mt < 2; mt++) {
            int mta = warpM * 2 + mt;
            #pragma unroll
            for (int jp = 0; jp < 4; jp++) {
                int j0 = 2 * jp, j1 = 2 * jp + 1;
                int c00 = (warpN * 8 + j0) * 8 + t * 2;   // cols of j0 (khi=0)
                int c10 = (warpN * 8 + j1) * 8 + t * 2;   // cols of j1 (khi=1)
                float* ca = acc[mt][j0];
                float* cb = acc[mt][j1];
                float va0 = fmaxf(ca[0] + s_cvec[c00],     0.f);
                float va1 = fmaxf(ca[1] + s_cvec[c00 + 1], 0.f);
                float va2 = fmaxf(ca[2] + s_cvec[c00],     0.f);
                float va3 = fmaxf(ca[3] + s_cvec[c00 + 1], 0.f);
                float vb0 = fmaxf(cb[0] + s_cvec[c10],     0.f);
                float vb1 = fmaxf(cb[1] + s_cvec[c10 + 1], 0.f);
                float vb2 = fmaxf(cb[2] + s_cvec[c10],     0.f);
                float vb3 = fmaxf(cb[3] + s_cvec[c10 + 1], 0.f);
                uint4 H, L;
                split2(va0, va1, H.x, L.x);   // slot0: khi0 (j0), row g
                split2(va2, va3, H.y, L.y);   // slot1: khi0, row g+8
                split2(vb0, vb1, H.z, L.z);   // slot2: khi1 (j1), row g
                split2(vb2, vb3, H.w, L.w);   // slot3: khi1, row g+8
                int key  = mta * 8 + warpN * 4 + jp;
                int addr = (key * 32 + lane) * 16;
                *(uint4*)(smc + OFF_AH + addr) = H;
                *(uint4*)(smc + OFF_AL + addr) = L;
                ca[0] = ca[1] = ca[2] = ca[3] = 0.f;
                cb[0] = cb[1] = cb[2] = cb[3] = 0.f;
            }
        }
        __syncthreads();

        // ---- layer 2 ----
        run_layer(smc, OFF_W2, acc, warpM, warpN, lane);

        // ---- epilogue 2: relu(C + b2) dot w3 -> per-row partials ----
        float sp[2][2] = {{0.f, 0.f}, {0.f, 0.f}};   // [mt][half]
        #pragma unroll
        for (int mt = 0; mt < 2; mt++) {
            #pragma unroll
            for (int j = 0; j < 8; j++) {
                int col0 = (warpN * 8 + j) * 8 + t * 2;
                float* c = acc[mt][j];
                float w0 = s_w3[col0], w1 = s_w3[col0 + 1];
                float bb0 = s_b2[col0], bb1 = s_b2[col0 + 1];
                sp[mt][0] += fmaxf(c[0] + bb0, 0.f) * w0
                           + fmaxf(c[1] + bb1, 0.f) * w1;
                sp[mt][1] += fmaxf(c[2] + bb0, 0.f) * w0
                           + fmaxf(c[3] + bb1, 0.f) * w1;
            }
        }
        #pragma unroll
        for (int off = 1; off < 4; off <<= 1) {
            #pragma unroll
            for (int mt = 0; mt < 2; mt++) {
                sp[mt][0] += __shfl_xor_sync(0xffffffffu, sp[mt][0], off);
                sp[mt][1] += __shfl_xor_sync(0xffffffffu, sp[mt][1], off);
            }
        }
        if (t == 0) {
            #pragma unroll
            for (int mt = 0; mt < 2; mt++) {
                int rbase = warpM * 32 + mt * 16;
                s_part[warpN * 128 + rbase + g]     = sp[mt][0];
                s_part[warpN * 128 + rbase + 8 + g] = sp[mt][1];
            }
        }
        __syncthreads();

        if (tid < 128) {
            int gr = base + tid;
            float v = s_part[tid] + s_part[128 + tid] + fb3;
            lg[kt] = v;
            if (gr < N) runmax = fmaxf(runmax, v);
        }
        __syncthreads();
    }

    // ---- phase-1 end: per-CTA max ----
    float m = runmax;
    #pragma unroll
    for (int s = 16; s > 0; s >>= 1) m = fmaxf(m, __shfl_xor_sync(0xffffffffu, m, s));
    if (lane == 0) s_red[wid] = m;
    __syncthreads();
    if (tid == 0) {
        float mx = s_red[0];
        #pragma unroll
        for (int i = 1; i < 8; i++) mx = fmaxf(mx, s_red[i]);
        g_ctamax[bid] = mx;
        __threadfence();
        atomicAdd(&g_bar, 1u);
        while (atomicAdd(&g_bar, 0u) < G) __nanosleep(64);
        __threadfence();
    }
    __syncthreads();

    // ---- phase 2: global max (deterministic serial), exp, per-CTA sum ----
    float gmax = g_ctamax[0];
    for (unsigned i = 1; i < G; i++) gmax = fmaxf(gmax, g_ctamax[i]);

    float psum = 0.f;
    if (tid < 128) {
        for (int kt = 0; kt < nt; kt++) {
            int gr = (bid + kt * (int)G) * TILE + tid;
            if (gr < N) {
                float e = __expf(lg[kt] - gmax);
                lg[kt] = e;
                psum += e;
            }
        }
    }
    #pragma unroll
    for (int s = 16; s > 0; s >>= 1) psum += __shfl_xor_sync(0xffffffffu, psum, s);
    if (lane == 0) s_red[wid] = psum;
    __syncthreads();
    if (tid == 0) {
        float sm = 0.f;
        #pragma unroll
        for (int i = 0; i < 8; i++) sm += s_red[i];
        g_ctasum[bid] = sm;
        __threadfence();
        atomicAdd(&g_bar, 1u);
        while (atomicAdd(&g_bar, 0u) < 2u * G) __nanosleep(64);
        __threadfence();
    }
    __syncthreads();

    // ---- phase 3: total sum (deterministic serial), normalize, write ----
    float tot = 0.f;
    for (unsigned i = 0; i < G; i++) tot += g_ctasum[i];
    const float inv = 1.f / tot;

    if (tid < 128) {
        for (int kt = 0; kt < nt; kt++) {
            int gr = (bid + kt * (int)G) * TILE + tid;
            if (gr < N) out[gr] = lg[kt] * inv;
        }
    }

    // ---- reset barrier state for next graph replay ----
    __syncthreads();
    if (tid == 0) {
        unsigned d = atomicAdd(&g_done, 1u);
        if (d == G - 1u) {
            atomicExch(&g_bar, 0u);
            atomicExch(&g_done, 0u);
            __threadfence();
        }
    }
}

// ---------------------------------------------------------------------------
extern "C" void kernel_launch(void* const* d_in, const int* in_sizes, int n_in,
                              void* d_out, int out_size)
{
    const float* node1 = (const float*)d_in[0];
    const float* u_rep = (const float*)d_in[1];

    // inputs: node1, u_rep, [num_neighs], W1, b1, W2, b2, W3, b3
    int wi = (n_in >= 9) ? 2 + (n_in - 8) : 2;
    if (in_sizes[wi] != 128 * 256) {
        for (int i = 2; i + 5 < n_in; i++)
            if (in_sizes[i] == 128 * 256) { wi = i; break; }
    }
    const float* W1 = (const float*)d_in[wi + 0];
    const float* b1 = (const float*)d_in[wi + 1];
    const float* W2 = (const float*)d_in[wi + 2];
    const float* b2 = (const float*)d_in[wi + 3];
    const float* W3 = (const float*)d_in[wi + 4];
    const float* b3 = (const float*)d_in[wi + 5];
    float* out = (float*)d_out;

    const int N      = in_sizes[0] / EMB;
    const int ntiles = (N + TILE - 1) / TILE;

    int nsm = 0;
    cudaDeviceGetAttribute(&nsm, cudaDevAttrMultiProcessorCount, 0);
    if (nsm <= 0) nsm = 148;
    int grid = ntiles < nsm ? ntiles : nsm;
    if (grid > GMAX) grid = GMAX;

    cudaFuncSetAttribute(k_fused, cudaFuncAttributeMaxDynamicSharedMemorySize,
                         SMEM_TOTAL);
    k_fused<<<grid, THREADS, SMEM_TOTAL>>>(node1, u_rep, W1, b1, W2, b2, W3, b3,
                                           out, N, ntiles);
}

// round 13
// speedup vs baseline: 1.3526x; 1.2367x over previous
#include <cuda_runtime.h>
#include <cuda_fp16.h>
#include <math_constants.h>
#include <cstdint>

// ---------------------------------------------------------------------------
// att = softmax( MLP3(concat(node1, u_rep)) ), N = 200000, d = 128.
// Single fused persistent kernel, 256 threads, 4Mx2N warps.
// R12: fp16 asymmetric 2-term split:  D = Ah*(Bh + Bl)
//   - A (activations) single-rounded to fp16 (error 2^-12, exact products)
//   - B (weights) split fp16 hi+lo (exact to 22 bits)
//   -> 2 MMAs per fragment-pair instead of 3; A-lo tile eliminated.
// All smem stores conflict-free STS.128 (R11 layout).
// ---------------------------------------------------------------------------

#define EMB     128
#define TILE    128
#define LMAX    16
#define GMAX    256
#define THREADS 256

// ---- smem layout (bytes) ----
#define OFF_W1   0        // 64KB: W1 frag-packed, 16B = [bh0 bh1 bl0 bl1]
#define OFF_W2   65536    // 64KB
#define OFF_AH   131072   // 32KB (fp16 A fragments)
#define OFF_CVEC 163840
#define OFF_B2   164352
#define OFF_W3   164864
#define OFF_PART 165376   // 1KB
#define OFF_RED  166400   // 32B
#define SMEM_TOTAL 166432

// ---------------- device scratch ----------------
__device__ float        g_ctamax[GMAX];
__device__ float        g_ctasum[GMAX];
__device__ unsigned int g_bar;
__device__ unsigned int g_done;

__device__ __forceinline__ uint32_t h2u(__half2 h) {
    return *reinterpret_cast<uint32_t*>(&h);
}

// mma.sync m16n8k16 fp16, fp32 accumulate in place (sm_80+ PTX)
__device__ __forceinline__ void mma_f16(float* c, const uint32_t* a,
                                        uint32_t b0, uint32_t b1) {
    asm volatile("mma.sync.aligned.m16n8k16.row.col.f32.f16.f16.f32 "
        "{%0,%1,%2,%3}, {%4,%5,%6,%7}, {%8,%9}, {%0,%1,%2,%3};"
        : "+f"(c[0]), "+f"(c[1]), "+f"(c[2]), "+f"(c[3])
        : "r"(a[0]), "r"(a[1]), "r"(a[2]), "r"(a[3]), "r"(b0), "r"(b1));
}

// Weight fragment address (byte offset of hi pair; lo pair at +8).
// B[n][k] "col" operand: lane=(n&7)*4+((k>>1)&3), sub=((k>>3)&1)*2+(k&1).
__device__ __forceinline__ int widx_hi(int n, int k) {
    int key = (((n >> 3) * 8 + (k >> 4)) * 32 + (n & 7) * 4 + ((k >> 1) & 3));
    int sub = ((k >> 3) & 1) * 2 + (k & 1);
    return key * 16 + sub * 2;
}

// ---------------------------------------------------------------------------
// One 128x128x128 layer slice: acc += Ah*Bh + Ah*Bl  (fp16, B exact)
// Term-major, j-inner ordering (dep distance 8).
// ---------------------------------------------------------------------------
__device__ __forceinline__ void run_layer(char* smc, int offW,
                                          float acc[2][8][4],
                                          int warpM, int warpN, int lane)
{
    #pragma unroll
    for (int ks = 0; ks < 8; ks++) {
        uint4 ah[2];
        #pragma unroll
        for (int mt = 0; mt < 2; mt++) {
            int mta  = warpM * 2 + mt;
            int aoff = ((mta * 8 + ks) * 32 + lane) * 16;
            ah[mt] = *(const uint4*)(smc + OFF_AH + aoff);
        }
        #pragma unroll
        for (int jb = 0; jb < 2; jb++) {
            uint4 b[4];
            #pragma unroll
            for (int j4 = 0; j4 < 4; j4++) {
                int ntg  = warpN * 8 + jb * 4 + j4;
                int boff = ((ntg * 8 + ks) * 32 + lane) * 16;
                b[j4] = *(const uint4*)(smc + offW + boff);  // bh.x bh.y bl.z bl.w
            }
            #pragma unroll
            for (int j4 = 0; j4 < 4; j4++)
                mma_f16(acc[0][jb * 4 + j4], (const uint32_t*)&ah[0], b[j4].x, b[j4].y);
            #pragma unroll
            for (int j4 = 0; j4 < 4; j4++)
                mma_f16(acc[1][jb * 4 + j4], (const uint32_t*)&ah[1], b[j4].x, b[j4].y);
            #pragma unroll
            for (int j4 = 0; j4 < 4; j4++)
                mma_f16(acc[0][jb * 4 + j4], (const uint32_t*)&ah[0], b[j4].z, b[j4].w);
            #pragma unroll
            for (int j4 = 0; j4 < 4; j4++)
                mma_f16(acc[1][jb * 4 + j4], (const uint32_t*)&ah[1], b[j4].z, b[j4].w);
        }
    }
}

// ---------------------------------------------------------------------------
__global__ __launch_bounds__(THREADS, 1)
void k_fused(const float* __restrict__ node1, const float* __restrict__ u_rep,
             const float* __restrict__ W1, const float* __restrict__ b1,
             const float* __restrict__ W2, const float* __restrict__ b2g,
             const float* __restrict__ w3g, const float* __restrict__ b3g,
             float* __restrict__ out, int N, int ntiles)
{
    extern __shared__ char smc[];
    const int tid   = threadIdx.x;
    const int wid   = tid >> 5;
    const int lane  = tid & 31;
    const int warpM = wid & 3;       // 4-way M split (32 rows each)
    const int warpN = wid >> 2;      // 2-way N split (64 cols each)
    const int g     = lane >> 2;
    const int t     = lane & 3;
    const int bid   = blockIdx.x;
    const unsigned G = gridDim.x;

    float* s_cvec = (float*)(smc + OFF_CVEC);
    float* s_b2   = (float*)(smc + OFF_B2);
    float* s_w3   = (float*)(smc + OFF_W3);
    float* s_part = (float*)(smc + OFF_PART);
    float* s_red  = (float*)(smc + OFF_RED);

    // ---- in-kernel weight split (fp16 hi/lo), fragment-packed ----
    for (int i = tid; i < EMB * EMB; i += THREADS) {
        int n = i >> 7, k = i & 127;
        int off = widx_hi(n, k);
        float w1 = W1[n * 256 + k];                   // node1 half of W1
        __half h1 = __float2half_rn(w1);
        *(__half*)(smc + OFF_W1 + off)     = h1;
        *(__half*)(smc + OFF_W1 + off + 8) = __float2half_rn(w1 - __half2float(h1));
        float w2 = W2[n * 128 + k];
        __half h2 = __float2half_rn(w2);
        *(__half*)(smc + OFF_W2 + off)     = h2;
        *(__half*)(smc + OFF_W2 + off + 8) = __float2half_rn(w2 - __half2float(h2));
    }
    // cvec = u_rep @ W1b^T + b1 (fp32, exact path)
    if (tid < 128) {
        float acc = b1[tid];
        const float* w = W1 + tid * 256 + 128;
        #pragma unroll 8
        for (int kk = 0; kk < 128; kk++) acc += u_rep[kk] * w[kk];
        s_cvec[tid] = acc;
        s_b2[tid]   = b2g[tid];
        s_w3[tid]   = w3g[tid];
    }
    __syncthreads();

    const float fb3 = b3g[0];
    const int nt = (ntiles > bid) ? (ntiles - 1 - bid) / (int)G + 1 : 0;
    float lg[LMAX];
    float runmax = -CUDART_INF_F;

    for (int kt = 0; kt < nt; kt++) {
        const int tile = bid + kt * (int)G;
        const int base = tile * TILE;

        // ---- stage: assemble fp16 A-fragments, conflict-free STS.128 ----
        // warp `wid` owns keys wid*8+ks (rows [wid*16, wid*16+16)); lane=(g,t).
        {
            const int r0 = base + wid * 16 + g;      // half=0 row
            const int r1 = r0 + 8;                   // half=1 row
            const float2* p0 = (const float2*)(node1 + (size_t)r0 * 128) + t;
            const float2* p1 = (const float2*)(node1 + (size_t)r1 * 128) + t;
            const bool ok0 = (r0 < N), ok1 = (r1 < N);
            const float2 z = make_float2(0.f, 0.f);
            #pragma unroll
            for (int ks = 0; ks < 8; ks++) {
                // float2 at k = ks*16 + khi*8 + 2t  (float2 idx = ks*8+khi*4+t)
                float2 d00 = ok0 ? p0[ks * 8]     : z;   // half0, khi0
                float2 d01 = ok0 ? p0[ks * 8 + 4] : z;   // half0, khi1
                float2 d10 = ok1 ? p1[ks * 8]     : z;   // half1, khi0
                float2 d11 = ok1 ? p1[ks * 8 + 4] : z;   // half1, khi1
                uint4 H;
                H.x = h2u(__floats2half2_rn(d00.x, d00.y));  // khi0,half0
                H.y = h2u(__floats2half2_rn(d10.x, d10.y));  // khi0,half1
                H.z = h2u(__floats2half2_rn(d01.x, d01.y));  // khi1,half0
                H.w = h2u(__floats2half2_rn(d11.x, d11.y));  // khi1,half1
                int addr = ((wid * 8 + ks) * 32 + lane) * 16;
                *(uint4*)(smc + OFF_AH + addr) = H;
            }
        }
        __syncthreads();

        // ---- layer 1 ----
        float acc[2][8][4];
        #pragma unroll
        for (int mt = 0; mt < 2; mt++)
            #pragma unroll
            for (int j = 0; j < 8; j++)
                #pragma unroll
                for (int e = 0; e < 4; e++) acc[mt][j][e] = 0.f;

        run_layer(smc, OFF_W1, acc, warpM, warpN, lane);
        __syncthreads();                 // A consumed; may be rewritten

        // ---- epilogue 1: relu(C + cvec) -> fp16 fragments, STS.128 ----
        #pragma unroll
        for (int mt = 0; mt < 2; mt++) {
            int mta = warpM * 2 + mt;
            #pragma unroll
            for (int jp = 0; jp < 4; jp++) {
                int j0 = 2 * jp, j1 = 2 * jp + 1;
                int c00 = (warpN * 8 + j0) * 8 + t * 2;   // cols of j0 (khi=0)
                int c10 = (warpN * 8 + j1) * 8 + t * 2;   // cols of j1 (khi=1)
                float* ca = acc[mt][j0];
                float* cb = acc[mt][j1];
                float va0 = fmaxf(ca[0] + s_cvec[c00],     0.f);
                float va1 = fmaxf(ca[1] + s_cvec[c00 + 1], 0.f);
                float va2 = fmaxf(ca[2] + s_cvec[c00],     0.f);
                float va3 = fmaxf(ca[3] + s_cvec[c00 + 1], 0.f);
                float vb0 = fmaxf(cb[0] + s_cvec[c10],     0.f);
                float vb1 = fmaxf(cb[1] + s_cvec[c10 + 1], 0.f);
                float vb2 = fmaxf(cb[2] + s_cvec[c10],     0.f);
                float vb3 = fmaxf(cb[3] + s_cvec[c10 + 1], 0.f);
                uint4 H;
                H.x = h2u(__floats2half2_rn(va0, va1));   // khi0 (j0), row g
                H.y = h2u(__floats2half2_rn(va2, va3));   // khi0, row g+8
                H.z = h2u(__floats2half2_rn(vb0, vb1));   // khi1 (j1), row g
                H.w = h2u(__floats2half2_rn(vb2, vb3));   // khi1, row g+8
                int key  = mta * 8 + warpN * 4 + jp;
                int addr = (key * 32 + lane) * 16;
                *(uint4*)(smc + OFF_AH + addr) = H;
                ca[0] = ca[1] = ca[2] = ca[3] = 0.f;
                cb[0] = cb[1] = cb[2] = cb[3] = 0.f;
            }
        }
        __syncthreads();

        // ---- layer 2 ----
        run_layer(smc, OFF_W2, acc, warpM, warpN, lane);

        // ---- epilogue 2: relu(C + b2) dot w3 -> per-row partials ----
        float sp[2][2] = {{0.f, 0.f}, {0.f, 0.f}};   // [mt][half]
        #pragma unroll
        for (int mt = 0; mt < 2; mt++) {
            #pragma unroll
            for (int j = 0; j < 8; j++) {
                int col0 = (warpN * 8 + j) * 8 + t * 2;
                float* c = acc[mt][j];
                float w0 = s_w3[col0], w1 = s_w3[col0 + 1];
                float bb0 = s_b2[col0], bb1 = s_b2[col0 + 1];
                sp[mt][0] += fmaxf(c[0] + bb0, 0.f) * w0
                           + fmaxf(c[1] + bb1, 0.f) * w1;
                sp[mt][1] += fmaxf(c[2] + bb0, 0.f) * w0
                           + fmaxf(c[3] + bb1, 0.f) * w1;
            }
        }
        #pragma unroll
        for (int off = 1; off < 4; off <<= 1) {
            #pragma unroll
            for (int mt = 0; mt < 2; mt++) {
                sp[mt][0] += __shfl_xor_sync(0xffffffffu, sp[mt][0], off);
                sp[mt][1] += __shfl_xor_sync(0xffffffffu, sp[mt][1], off);
            }
        }
        if (t == 0) {
            #pragma unroll
            for (int mt = 0; mt < 2; mt++) {
                int rbase = warpM * 32 + mt * 16;
                s_part[warpN * 128 + rbase + g]     = sp[mt][0];
                s_part[warpN * 128 + rbase + 8 + g] = sp[mt][1];
            }
        }
        __syncthreads();

        if (tid < 128) {
            int gr = base + tid;
            float v = s_part[tid] + s_part[128 + tid] + fb3;
            lg[kt] = v;
            if (gr < N) runmax = fmaxf(runmax, v);
        }
        __syncthreads();
    }

    // ---- phase-1 end: per-CTA max ----
    float m = runmax;
    #pragma unroll
    for (int s = 16; s > 0; s >>= 1) m = fmaxf(m, __shfl_xor_sync(0xffffffffu, m, s));
    if (lane == 0) s_red[wid] = m;
    __syncthreads();
    if (tid == 0) {
        float mx = s_red[0];
        #pragma unroll
        for (int i = 1; i < 8; i++) mx = fmaxf(mx, s_red[i]);
        g_ctamax[bid] = mx;
        __threadfence();
        atomicAdd(&g_bar, 1u);
        while (atomicAdd(&g_bar, 0u) < G) __nanosleep(64);
        __threadfence();
    }
    __syncthreads();

    // ---- phase 2: global max (deterministic serial), exp, per-CTA sum ----
    float gmax = g_ctamax[0];
    for (unsigned i = 1; i < G; i++) gmax = fmaxf(gmax, g_ctamax[i]);

    float psum = 0.f;
    if (tid < 128) {
        for (int kt = 0; kt < nt; kt++) {
            int gr = (bid + kt * (int)G) * TILE + tid;
            if (gr < N) {
                float e = __expf(lg[kt] - gmax);
                lg[kt] = e;
                psum += e;
            }
        }
    }
    #pragma unroll
    for (int s = 16; s > 0; s >>= 1) psum += __shfl_xor_sync(0xffffffffu, psum, s);
    if (lane == 0) s_red[wid] = psum;
    __syncthreads();
    if (tid == 0) {
        float sm = 0.f;
        #pragma unroll
        for (int i = 0; i < 8; i++) sm += s_red[i];
        g_ctasum[bid] = sm;
        __threadfence();
        atomicAdd(&g_bar, 1u);
        while (atomicAdd(&g_bar, 0u) < 2u * G) __nanosleep(64);
        __threadfence();
    }
    __syncthreads();

    // ---- phase 3: total sum (deterministic serial), normalize, write ----
    float tot = 0.f;
    for (unsigned i = 0; i < G; i++) tot += g_ctasum[i];
    const float inv = 1.f / tot;

    if (tid < 128) {
        for (int kt = 0; kt < nt; kt++) {
            int gr = (bid + kt * (int)G) * TILE + tid;
            if (gr < N) out[gr] = lg[kt] * inv;
        }
    }

    // ---- reset barrier state for next graph replay ----
    __syncthreads();
    if (tid == 0) {
        unsigned d = atomicAdd(&g_done, 1u);
        if (d == G - 1u) {
            atomicExch(&g_bar, 0u);
            atomicExch(&g_done, 0u);
            __threadfence();
        }
    }
}

// ---------------------------------------------------------------------------
extern "C" void kernel_launch(void* const* d_in, const int* in_sizes, int n_in,
                              void* d_out, int out_size)
{
    const float* node1 = (const float*)d_in[0];
    const float* u_rep = (const float*)d_in[1];

    // inputs: node1, u_rep, [num_neighs], W1, b1, W2, b2, W3, b3
    int wi = (n_in >= 9) ? 2 + (n_in - 8) : 2;
    if (in_sizes[wi] != 128 * 256) {
        for (int i = 2; i + 5 < n_in; i++)
            if (in_sizes[i] == 128 * 256) { wi = i; break; }
    }
    const float* W1 = (const float*)d_in[wi + 0];
    const float* b1 = (const float*)d_in[wi + 1];
    const float* W2 = (const float*)d_in[wi + 2];
    const float* b2 = (const float*)d_in[wi + 3];
    const float* W3 = (const float*)d_in[wi + 4];
    const float* b3 = (const float*)d_in[wi + 5];
    float* out = (float*)d_out;

    const int N      = in_sizes[0] / EMB;
    const int ntiles = (N + TILE - 1) / TILE;

    int nsm = 0;
    cudaDeviceGetAttribute(&nsm, cudaDevAttrMultiProcessorCount, 0);
    if (nsm <= 0) nsm = 148;
    int grid = ntiles < nsm ? ntiles : nsm;
    if (grid > GMAX) grid = GMAX;

    cudaFuncSetAttribute(k_fused, cudaFuncAttributeMaxDynamicSharedMemorySize,
                         SMEM_TOTAL);
    k_fused<<<grid, THREADS, SMEM_TOTAL>>>(node1, u_rep, W1, b1, W2, b2, W3, b3,
                                           out, N, ntiles);
}

// round 14
// speedup vs baseline: 1.7231x; 1.2739x over previous
#include <cuda_runtime.h>
#include <cuda_fp16.h>
#include <math_constants.h>
#include <cstdint>

// ---------------------------------------------------------------------------
// att = softmax( MLP3(concat(node1, u_rep)) ), N = 200000, d = 128.
// Single fused persistent kernel, 256 threads, 4Mx2N warps.
// R13: pure fp16 mma (1 term):  D = Ah*Bh
//   - calibrated error model: rel_err ~ 1.8e-4 (A-only split measured 1.27e-4)
//   - B fragments 8B -> weight smem halves, B loads are LDS.64
// All smem stores conflict-free STS.128 (R11 layout).
// ---------------------------------------------------------------------------

#define EMB     128
#define TILE    128
#define LMAX    16
#define GMAX    256
#define THREADS 256

// ---- smem layout (bytes) ----
#define OFF_W1   0        // 32KB: W1 frag-packed fp16, 8B/frag = [bh0 bh1]
#define OFF_W2   32768    // 32KB
#define OFF_AH   65536    // 32KB (fp16 A fragments, 16B/frag)
#define OFF_CVEC 98304
#define OFF_B2   98816
#define OFF_W3   99328
#define OFF_PART 99840    // 1KB
#define OFF_RED  100864   // 32B
#define SMEM_TOTAL 100896

// ---------------- device scratch ----------------
__device__ float        g_ctamax[GMAX];
__device__ float        g_ctasum[GMAX];
__device__ unsigned int g_bar;
__device__ unsigned int g_done;

__device__ __forceinline__ uint32_t h2u(__half2 h) {
    return *reinterpret_cast<uint32_t*>(&h);
}

// mma.sync m16n8k16 fp16, fp32 accumulate in place (sm_80+ PTX)
__device__ __forceinline__ void mma_f16(float* c, const uint32_t* a,
                                        uint32_t b0, uint32_t b1) {
    asm volatile("mma.sync.aligned.m16n8k16.row.col.f32.f16.f16.f32 "
        "{%0,%1,%2,%3}, {%4,%5,%6,%7}, {%8,%9}, {%0,%1,%2,%3};"
        : "+f"(c[0]), "+f"(c[1]), "+f"(c[2]), "+f"(c[3])
        : "r"(a[0]), "r"(a[1]), "r"(a[2]), "r"(a[3]), "r"(b0), "r"(b1));
}

// Weight fragment address (byte offset), 8B per fragment now.
// B[n][k] "col" operand: lane=(n&7)*4+((k>>1)&3), sub=((k>>3)&1)*2+(k&1).
__device__ __forceinline__ int widx(int n, int k) {
    int key = (((n >> 3) * 8 + (k >> 4)) * 32 + (n & 7) * 4 + ((k >> 1) & 3));
    int sub = ((k >> 3) & 1) * 2 + (k & 1);
    return key * 8 + sub * 2;
}

// ---------------------------------------------------------------------------
// One 128x128x128 layer slice: acc += Ah*Bh  (pure fp16)
// j-inner ordering (dep distance 8).
// ---------------------------------------------------------------------------
__device__ __forceinline__ void run_layer(char* smc, int offW,
                                          float acc[2][8][4],
                                          int warpM, int warpN, int lane)
{
    #pragma unroll
    for (int ks = 0; ks < 8; ks++) {
        uint4 ah[2];
        #pragma unroll
        for (int mt = 0; mt < 2; mt++) {
            int mta  = warpM * 2 + mt;
            int aoff = ((mta * 8 + ks) * 32 + lane) * 16;
            ah[mt] = *(const uint4*)(smc + OFF_AH + aoff);
        }
        #pragma unroll
        for (int jb = 0; jb < 2; jb++) {
            uint2 b[4];
            #pragma unroll
            for (int j4 = 0; j4 < 4; j4++) {
                int ntg  = warpN * 8 + jb * 4 + j4;
                int boff = ((ntg * 8 + ks) * 32 + lane) * 8;
                b[j4] = *(const uint2*)(smc + offW + boff);   // bh0 bh1
            }
            #pragma unroll
            for (int j4 = 0; j4 < 4; j4++)
                mma_f16(acc[0][jb * 4 + j4], (const uint32_t*)&ah[0], b[j4].x, b[j4].y);
            #pragma unroll
            for (int j4 = 0; j4 < 4; j4++)
                mma_f16(acc[1][jb * 4 + j4], (const uint32_t*)&ah[1], b[j4].x, b[j4].y);
        }
    }
}

// ---------------------------------------------------------------------------
__global__ __launch_bounds__(THREADS, 1)
void k_fused(const float* __restrict__ node1, const float* __restrict__ u_rep,
             const float* __restrict__ W1, const float* __restrict__ b1,
             const float* __restrict__ W2, const float* __restrict__ b2g,
             const float* __restrict__ w3g, const float* __restrict__ b3g,
             float* __restrict__ out, int N, int ntiles)
{
    extern __shared__ char smc[];
    const int tid   = threadIdx.x;
    const int wid   = tid >> 5;
    const int lane  = tid & 31;
    const int warpM = wid & 3;       // 4-way M split (32 rows each)
    const int warpN = wid >> 2;      // 2-way N split (64 cols each)
    const int g     = lane >> 2;
    const int t     = lane & 3;
    const int bid   = blockIdx.x;
    const unsigned G = gridDim.x;

    float* s_cvec = (float*)(smc + OFF_CVEC);
    float* s_b2   = (float*)(smc + OFF_B2);
    float* s_w3   = (float*)(smc + OFF_W3);
    float* s_part = (float*)(smc + OFF_PART);
    float* s_red  = (float*)(smc + OFF_RED);

    // ---- in-kernel weight conversion (fp16), fragment-packed ----
    for (int i = tid; i < EMB * EMB; i += THREADS) {
        int n = i >> 7, k = i & 127;
        int off = widx(n, k);
        *(__half*)(smc + OFF_W1 + off) = __float2half_rn(W1[n * 256 + k]);
        *(__half*)(smc + OFF_W2 + off) = __float2half_rn(W2[n * 128 + k]);
    }
    // cvec = u_rep @ W1b^T + b1 (fp32, exact path)
    if (tid < 128) {
        float acc = b1[tid];
        const float* w = W1 + tid * 256 + 128;
        #pragma unroll 8
        for (int kk = 0; kk < 128; kk++) acc += u_rep[kk] * w[kk];
        s_cvec[tid] = acc;
        s_b2[tid]   = b2g[tid];
        s_w3[tid]   = w3g[tid];
    }
    __syncthreads();

    const float fb3 = b3g[0];
    const int nt = (ntiles > bid) ? (ntiles - 1 - bid) / (int)G + 1 : 0;
    float lg[LMAX];
    float runmax = -CUDART_INF_F;

    for (int kt = 0; kt < nt; kt++) {
        const int tile = bid + kt * (int)G;
        const int base = tile * TILE;

        // ---- stage: assemble fp16 A-fragments, conflict-free STS.128 ----
        // warp `wid` owns keys wid*8+ks (rows [wid*16, wid*16+16)); lane=(g,t).
        {
            const int r0 = base + wid * 16 + g;      // half=0 row
            const int r1 = r0 + 8;                   // half=1 row
            const float2* p0 = (const float2*)(node1 + (size_t)r0 * 128) + t;
            const float2* p1 = (const float2*)(node1 + (size_t)r1 * 128) + t;
            const bool ok0 = (r0 < N), ok1 = (r1 < N);
            const float2 z = make_float2(0.f, 0.f);
            #pragma unroll
            for (int ks = 0; ks < 8; ks++) {
                // float2 at k = ks*16 + khi*8 + 2t  (float2 idx = ks*8+khi*4+t)
                float2 d00 = ok0 ? p0[ks * 8]     : z;   // half0, khi0
                float2 d01 = ok0 ? p0[ks * 8 + 4] : z;   // half0, khi1
                float2 d10 = ok1 ? p1[ks * 8]     : z;   // half1, khi0
                float2 d11 = ok1 ? p1[ks * 8 + 4] : z;   // half1, khi1
                uint4 H;
                H.x = h2u(__floats2half2_rn(d00.x, d00.y));  // khi0,half0
                H.y = h2u(__floats2half2_rn(d10.x, d10.y));  // khi0,half1
                H.z = h2u(__floats2half2_rn(d01.x, d01.y));  // khi1,half0
                H.w = h2u(__floats2half2_rn(d11.x, d11.y));  // khi1,half1
                int addr = ((wid * 8 + ks) * 32 + lane) * 16;
                *(uint4*)(smc + OFF_AH + addr) = H;
            }
        }
        __syncthreads();

        // ---- layer 1 ----
        float acc[2][8][4];
        #pragma unroll
        for (int mt = 0; mt < 2; mt++)
            #pragma unroll
            for (int j = 0; j < 8; j++)
                #pragma unroll
                for (int e = 0; e < 4; e++) acc[mt][j][e] = 0.f;

        run_layer(smc, OFF_W1, acc, warpM, warpN, lane);
        __syncthreads();                 // A consumed; may be rewritten

        // ---- epilogue 1: relu(C + cvec) -> fp16 fragments, STS.128 ----
        #pragma unroll
        for (int mt = 0; mt < 2; mt++) {
            int mta = warpM * 2 + mt;
            #pragma unroll
            for (int jp = 0; jp < 4; jp++) {
                int j0 = 2 * jp, j1 = 2 * jp + 1;
                int c00 = (warpN * 8 + j0) * 8 + t * 2;   // cols of j0 (khi=0)
                int c10 = (warpN * 8 + j1) * 8 + t * 2;   // cols of j1 (khi=1)
                float* ca = acc[mt][j0];
                float* cb = acc[mt][j1];
                float va0 = fmaxf(ca[0] + s_cvec[c00],     0.f);
                float va1 = fmaxf(ca[1] + s_cvec[c00 + 1], 0.f);
                float va2 = fmaxf(ca[2] + s_cvec[c00],     0.f);
                float va3 = fmaxf(ca[3] + s_cvec[c00 + 1], 0.f);
                float vb0 = fmaxf(cb[0] + s_cvec[c10],     0.f);
                float vb1 = fmaxf(cb[1] + s_cvec[c10 + 1], 0.f);
                float vb2 = fmaxf(cb[2] + s_cvec[c10],     0.f);
                float vb3 = fmaxf(cb[3] + s_cvec[c10 + 1], 0.f);
                uint4 H;
                H.x = h2u(__floats2half2_rn(va0, va1));   // khi0 (j0), row g
                H.y = h2u(__floats2half2_rn(va2, va3));   // khi0, row g+8
                H.z = h2u(__floats2half2_rn(vb0, vb1));   // khi1 (j1), row g
                H.w = h2u(__floats2half2_rn(vb2, vb3));   // khi1, row g+8
                int key  = mta * 8 + warpN * 4 + jp;
                int addr = (key * 32 + lane) * 16;
                *(uint4*)(smc + OFF_AH + addr) = H;
                ca[0] = ca[1] = ca[2] = ca[3] = 0.f;
                cb[0] = cb[1] = cb[2] = cb[3] = 0.f;
            }
        }
        __syncthreads();

        // ---- layer 2 ----
        run_layer(smc, OFF_W2, acc, warpM, warpN, lane);

        // ---- epilogue 2: relu(C + b2) dot w3 -> per-row partials ----
        float sp[2][2] = {{0.f, 0.f}, {0.f, 0.f}};   // [mt][half]
        #pragma unroll
        for (int mt = 0; mt < 2; mt++) {
            #pragma unroll
            for (int j = 0; j < 8; j++) {
                int col0 = (warpN * 8 + j) * 8 + t * 2;
                float* c = acc[mt][j];
                float w0 = s_w3[col0], w1 = s_w3[col0 + 1];
                float bb0 = s_b2[col0], bb1 = s_b2[col0 + 1];
                sp[mt][0] += fmaxf(c[0] + bb0, 0.f) * w0
                           + fmaxf(c[1] + bb1, 0.f) * w1;
                sp[mt][1] += fmaxf(c[2] + bb0, 0.f) * w0
                           + fmaxf(c[3] + bb1, 0.f) * w1;
            }
        }
        #pragma unroll
        for (int off = 1; off < 4; off <<= 1) {
            #pragma unroll
            for (int mt = 0; mt < 2; mt++) {
                sp[mt][0] += __shfl_xor_sync(0xffffffffu, sp[mt][0], off);
                sp[mt][1] += __shfl_xor_sync(0xffffffffu, sp[mt][1], off);
            }
        }
        if (t == 0) {
            #pragma unroll
            for (int mt = 0; mt < 2; mt++) {
                int rbase = warpM * 32 + mt * 16;
                s_part[warpN * 128 + rbase + g]     = sp[mt][0];
                s_part[warpN * 128 + rbase + 8 + g] = sp[mt][1];
            }
        }
        __syncthreads();

        if (tid < 128) {
            int gr = base + tid;
            float v = s_part[tid] + s_part[128 + tid] + fb3;
            lg[kt] = v;
            if (gr < N) runmax = fmaxf(runmax, v);
        }
        __syncthreads();
    }

    // ---- phase-1 end: per-CTA max ----
    float m = runmax;
    #pragma unroll
    for (int s = 16; s > 0; s >>= 1) m = fmaxf(m, __shfl_xor_sync(0xffffffffu, m, s));
    if (lane == 0) s_red[wid] = m;
    __syncthreads();
    if (tid == 0) {
        float mx = s_red[0];
        #pragma unroll
        for (int i = 1; i < 8; i++) mx = fmaxf(mx, s_red[i]);
        g_ctamax[bid] = mx;
        __threadfence();
        atomicAdd(&g_bar, 1u);
        while (atomicAdd(&g_bar, 0u) < G) __nanosleep(64);
        __threadfence();
    }
    __syncthreads();

    // ---- phase 2: global max (deterministic serial), exp, per-CTA sum ----
    float gmax = g_ctamax[0];
    for (unsigned i = 1; i < G; i++) gmax = fmaxf(gmax, g_ctamax[i]);

    float psum = 0.f;
    if (tid < 128) {
        for (int kt = 0; kt < nt; kt++) {
            int gr = (bid + kt * (int)G) * TILE + tid;
            if (gr < N) {
                float e = __expf(lg[kt] - gmax);
                lg[kt] = e;
                psum += e;
            }
        }
    }
    #pragma unroll
    for (int s = 16; s > 0; s >>= 1) psum += __shfl_xor_sync(0xffffffffu, psum, s);
    if (lane == 0) s_red[wid] = psum;
    __syncthreads();
    if (tid == 0) {
        float sm = 0.f;
        #pragma unroll
        for (int i = 0; i < 8; i++) sm += s_red[i];
        g_ctasum[bid] = sm;
        __threadfence();
        atomicAdd(&g_bar, 1u);
        while (atomicAdd(&g_bar, 0u) < 2u * G) __nanosleep(64);
        __threadfence();
    }
    __syncthreads();

    // ---- phase 3: total sum (deterministic serial), normalize, write ----
    float tot = 0.f;
    for (unsigned i = 0; i < G; i++) tot += g_ctasum[i];
    const float inv = 1.f / tot;

    if (tid < 128) {
        for (int kt = 0; kt < nt; kt++) {
            int gr = (bid + kt * (int)G) * TILE + tid;
            if (gr < N) out[gr] = lg[kt] * inv;
        }
    }

    // ---- reset barrier state for next graph replay ----
    __syncthreads();
    if (tid == 0) {
        unsigned d = atomicAdd(&g_done, 1u);
        if (d == G - 1u) {
            atomicExch(&g_bar, 0u);
            atomicExch(&g_done, 0u);
            __threadfence();
        }
    }
}

// ---------------------------------------------------------------------------
extern "C" void kernel_launch(void* const* d_in, const int* in_sizes, int n_in,
                              void* d_out, int out_size)
{
    const float* node1 = (const float*)d_in[0];
    const float* u_rep = (const float*)d_in[1];

    // inputs: node1, u_rep, [num_neighs], W1, b1, W2, b2, W3, b3
    int wi = (n_in >= 9) ? 2 + (n_in - 8) : 2;
    if (in_sizes[wi] != 128 * 256) {
        for (int i = 2; i + 5 < n_in; i++)
            if (in_sizes[i] == 128 * 256) { wi = i; break; }
    }
    const float* W1 = (const float*)d_in[wi + 0];
    const float* b1 = (const float*)d_in[wi + 1];
    const float* W2 = (const float*)d_in[wi + 2];
    const float* b2 = (const float*)d_in[wi + 3];
    const float* W3 = (const float*)d_in[wi + 4];
    const float* b3 = (const float*)d_in[wi + 5];
    float* out = (float*)d_out;

    const int N      = in_sizes[0] / EMB;
    const int ntiles = (N + TILE - 1) / TILE;

    int nsm = 0;
    cudaDeviceGetAttribute(&nsm, cudaDevAttrMultiProcessorCount, 0);
    if (nsm <= 0) nsm = 148;
    int grid = ntiles < nsm ? ntiles : nsm;
    if (grid > GMAX) grid = GMAX;

    cudaFuncSetAttribute(k_fused, cudaFuncAttributeMaxDynamicSharedMemorySize,
                         SMEM_TOTAL);
    k_fused<<<grid, THREADS, SMEM_TOTAL>>>(node1, u_rep, W1, b1, W2, b2, W3, b3,
                                           out, N, ntiles);
}